// round 4
// baseline (speedup 1.0000x reference)
#include <cuda_runtime.h>
#include <cstdint>

// MaxUnpooling2D, fixed shapes:
//   updates [16,64,64,256] f32, mask [16,64,64,256] i32
//   out     [16,128,128,256] f32   (oH=oW=128, C=256)
// mask = (y*128 + x)*256 + c with y = 2h+dy, x = 2w+dx, dy,dx in {0,1}.
// Gather/demux: each thread handles TWO consecutive float4 channel-groups of
// one pooled cell, writes all 4 window slots for both (exactly-once coverage
// of the output; no zero pass, no atomics).
// Slot index k = dy*2+dx = ((m>>14)&2) | ((m>>8)&1)  (parity bits of y, x).
//
// R2: 59.0us kernel, DRAM 71.6%, issue 16% -> add MLP (4 front-batched
// LDG.128/thread) + streaming cache hints (.cs) for read-once/write-once data.

__global__ void __launch_bounds__(256, 8)
maxunpool_kernel(const float4* __restrict__ upd,
                 const int4*  __restrict__ mask,
                 float4*      __restrict__ out)
{
    unsigned i = blockIdx.x * blockDim.x + threadIdx.x;  // < 2^21 exactly
    unsigned g = i << 1;                                 // first float4 group

    // Front-batched loads: 4 independent LDG.128
    float4 u0 = __ldcs(&upd[g]);
    float4 u1 = __ldcs(&upd[g + 1]);
    int4   m0 = __ldcs(&mask[g]);
    int4   m1 = __ldcs(&mask[g + 1]);

    int a0 = ((m0.x >> 14) & 2) | ((m0.x >> 8) & 1);
    int a1 = ((m0.y >> 14) & 2) | ((m0.y >> 8) & 1);
    int a2 = ((m0.z >> 14) & 2) | ((m0.z >> 8) & 1);
    int a3 = ((m0.w >> 14) & 2) | ((m0.w >> 8) & 1);
    int b0 = ((m1.x >> 14) & 2) | ((m1.x >> 8) & 1);
    int b1 = ((m1.y >> 14) & 2) | ((m1.y >> 8) & 1);
    int b2 = ((m1.z >> 14) & 2) | ((m1.z >> 8) & 1);
    int b3 = ((m1.w >> 14) & 2) | ((m1.w >> 8) & 1);

    // g = b<<18 | h<<12 | w<<6 | c4   (b<16; h,w,c4 < 64)
    // out float4 base = b<<20 | h<<14 | w<<7 | c4
    unsigned base = ( g         & 63u)
                  | ((g >>  6) & 63u) << 7
                  | ((g >> 12) & 63u) << 14
                  | ( g >> 18)        << 20;

    // dy stride = 1<<13 float4s; dx stride = 1<<6 float4s.
    #pragma unroll
    for (int k = 0; k < 4; k++) {
        unsigned off = base + ((unsigned)(k >> 1) << 13) + ((unsigned)(k & 1) << 6);
        float4 o0, o1;
        o0.x = (a0 == k) ? u0.x : 0.0f;
        o0.y = (a1 == k) ? u0.y : 0.0f;
        o0.z = (a2 == k) ? u0.z : 0.0f;
        o0.w = (a3 == k) ? u0.w : 0.0f;
        o1.x = (b0 == k) ? u1.x : 0.0f;
        o1.y = (b1 == k) ? u1.y : 0.0f;
        o1.z = (b2 == k) ? u1.z : 0.0f;
        o1.w = (b3 == k) ? u1.w : 0.0f;
        __stcs(&out[off],     o0);
        __stcs(&out[off + 1], o1);
    }
}

extern "C" void kernel_launch(void* const* d_in, const int* in_sizes, int n_in,
                              void* d_out, int out_size)
{
    const float4* upd  = (const float4*)d_in[0];
    const int4*   mask = (const int4*)d_in[1];
    float4*       out  = (float4*)d_out;

    // total threads = 16*64*64*(256/4)/2 = 2,097,152
    const int total = 16 * 64 * 64 * 64 / 2;
    const int tpb = 256;
    maxunpool_kernel<<<total / tpb, tpb>>>(upd, mask, out);
}

// round 7
// speedup vs baseline: 1.2951x; 1.2951x over previous
#include <cuda_runtime.h>
#include <cstdint>

// MaxUnpooling2D, fixed shapes:
//   updates [16,64,64,256] f32, mask [16,64,64,256] i32
//   out     [16,128,128,256] f32   (oH=oW=128, C=256)
// mask = (y*128 + x)*256 + c with y = 2h+dy, x = 2w+dx, dy,dx in {0,1}.
// Gather/demux: thread reads update+mask for float4 groups g0 and g1
// (BLOCK-strided: g0, g0+256, so each warp instruction stays 128B-contiguous)
// and writes all 4 window slots for both. Exactly-once output coverage:
// no zero pass, no atomics.
// Slot index k = dy*2+dx = ((m>>14)&2) | ((m>>8)&1)  (parity bits of y, x).
//
// R3 post-mortem: adjacent-element unroll made every warp LDG/STG stride-2
// -> 2x L1 wavefronts, DRAM starved (54.7%). Fixed by block-strided unroll.
// .cs hints: all streams touched once; output (268MB) > L2 (126MB), so
// evict-first avoids L2 thrash between the write stream and read sectors.

__global__ void __launch_bounds__(256, 8)
maxunpool_kernel(const float4* __restrict__ upd,
                 const int4*  __restrict__ mask,
                 float4*      __restrict__ out)
{
    unsigned g0 = blockIdx.x * 512u + threadIdx.x;  // first float4 group
    unsigned g1 = g0 + 256u;                        // second, block-strided

    // Front-batched loads: 4 independent, warp-contiguous LDG.128
    float4 u0 = __ldcs(&upd[g0]);
    float4 u1 = __ldcs(&upd[g1]);
    int4   m0 = __ldcs(&mask[g0]);
    int4   m1 = __ldcs(&mask[g1]);

    int a0 = ((m0.x >> 14) & 2) | ((m0.x >> 8) & 1);
    int a1 = ((m0.y >> 14) & 2) | ((m0.y >> 8) & 1);
    int a2 = ((m0.z >> 14) & 2) | ((m0.z >> 8) & 1);
    int a3 = ((m0.w >> 14) & 2) | ((m0.w >> 8) & 1);
    int b0 = ((m1.x >> 14) & 2) | ((m1.x >> 8) & 1);
    int b1 = ((m1.y >> 14) & 2) | ((m1.y >> 8) & 1);
    int b2 = ((m1.z >> 14) & 2) | ((m1.z >> 8) & 1);
    int b3 = ((m1.w >> 14) & 2) | ((m1.w >> 8) & 1);

    // g = b<<18 | h<<12 | w<<6 | c4  (b<16; h,w,c4 < 64)
    // out float4 base = b<<20 | h<<14 | w<<7 | c4
    unsigned base0 = ( g0         & 63u)
                   | ((g0 >>  6) & 63u) << 7
                   | ((g0 >> 12) & 63u) << 14
                   | ( g0 >> 18)        << 20;
    unsigned base1 = ( g1         & 63u)
                   | ((g1 >>  6) & 63u) << 7
                   | ((g1 >> 12) & 63u) << 14
                   | ( g1 >> 18)        << 20;

    // dy stride = 1<<13 float4s; dx stride = 1<<6 float4s.
    #pragma unroll
    for (int k = 0; k < 4; k++) {
        unsigned d = ((unsigned)(k >> 1) << 13) + ((unsigned)(k & 1) << 6);
        float4 o0, o1;
        o0.x = (a0 == k) ? u0.x : 0.0f;
        o0.y = (a1 == k) ? u0.y : 0.0f;
        o0.z = (a2 == k) ? u0.z : 0.0f;
        o0.w = (a3 == k) ? u0.w : 0.0f;
        o1.x = (b0 == k) ? u1.x : 0.0f;
        o1.y = (b1 == k) ? u1.y : 0.0f;
        o1.z = (b2 == k) ? u1.z : 0.0f;
        o1.w = (b3 == k) ? u1.w : 0.0f;
        __stcs(&out[base0 + d], o0);
        __stcs(&out[base1 + d], o1);
    }
}

extern "C" void kernel_launch(void* const* d_in, const int* in_sizes, int n_in,
                              void* d_out, int out_size)
{
    const float4* upd  = (const float4*)d_in[0];
    const int4*   mask = (const int4*)d_in[1];
    float4*       out  = (float4*)d_out;

    // total float4 groups = 16*64*64*(256/4) = 4,194,304; 512 per block
    const int blocks = 16 * 64 * 64 * 64 / 512;  // 8192
    maxunpool_kernel<<<blocks, 256>>>(upd, mask, out);
}